// round 6
// baseline (speedup 1.0000x reference)
#include <cuda_runtime.h>
#include <cuda_fp16.h>
#include <cstdint>
#include <cstddef>

// ---------------------------------------------------------------------------
// LSTM: x[256,512,512] -> LSTM(H=1024), last hidden -> FC(512). out fp32 [256,512]
// Phases: prep(convert fp32->fp16, bias, zero state)
//         xproj: xW = x @ W_ih^T + bias   (mma.sync fp16, fp32 out, [t][b][u])
//         recurrence: 128 persistent CTAs, W_hh slice smem-stationary,
//                     per-step mma + pointwise + grid barrier
//         fc: fp32 tiled GEMM from fp32 hT snapshot
// ---------------------------------------------------------------------------

#define DEVFN __device__ __forceinline__

// ------------------------- static device scratch ---------------------------
__device__ __half  g_x[67108864];        // x fp16 [b*512+t][512]
__device__ __half  g_Wih[2097152];       // W_ih fp16 [4096][512]
__device__ __half  g_Whh[4194304];       // W_hh fp16 [4096][1024]
__device__ float   g_bias[4096];         // b_ih + b_hh
__device__ float   g_xwi[134217728];     // per-gate xW fp32, [t][b][unit]
__device__ float   g_xwf[134217728];
__device__ float   g_xwg[134217728];
__device__ float   g_xwo[134217728];
__device__ __half  g_h[2 * 262144];      // double-buffered hidden fp16 [b][u]
__device__ float   g_c[262144];          // cell state fp32
__device__ float   g_hT[262144];         // final hidden fp32
__device__ unsigned g_bar;               // grid barrier (monotonic)

// ------------------------------ helpers ------------------------------------
DEVFN void ldmx4(unsigned &r0, unsigned &r1, unsigned &r2, unsigned &r3,
                 const void* p) {
    unsigned a = (unsigned)__cvta_generic_to_shared(p);
    asm volatile("ldmatrix.sync.aligned.m8n8.x4.shared.b16 {%0,%1,%2,%3}, [%4];"
                 : "=r"(r0), "=r"(r1), "=r"(r2), "=r"(r3) : "r"(a));
}

DEVFN void mma16816(float* c, const unsigned* a, const unsigned* b) {
    asm volatile(
        "mma.sync.aligned.m16n8k16.row.col.f32.f16.f16.f32 "
        "{%0,%1,%2,%3}, {%4,%5,%6,%7}, {%8,%9}, {%0,%1,%2,%3};"
        : "+f"(c[0]), "+f"(c[1]), "+f"(c[2]), "+f"(c[3])
        : "r"(a[0]), "r"(a[1]), "r"(a[2]), "r"(a[3]), "r"(b[0]), "r"(b[1]));
}

DEVFN float fsig(float x)  { return 1.f / (1.f + __expf(-x)); }
DEVFN float ftanh(float x) { return 1.f - 2.f / (__expf(2.f * x) + 1.f); }

// ------------------------------- prep kernel -------------------------------
__global__ void prep_kernel(const float* __restrict__ x,
                            const float* __restrict__ Wih,
                            const float* __restrict__ Whh,
                            const float* __restrict__ bih,
                            const float* __restrict__ bhh) {
    size_t i0 = (size_t)blockIdx.x * blockDim.x + threadIdx.x;
    size_t stride = (size_t)gridDim.x * blockDim.x;
    for (size_t i = i0; i < 33554432u; i += stride) {
        float2 v = ((const float2*)x)[i];
        ((__half2*)g_x)[i] = __floats2half2_rn(v.x, v.y);
    }
    for (size_t i = i0; i < 1048576u; i += stride) {
        float2 v = ((const float2*)Wih)[i];
        ((__half2*)g_Wih)[i] = __floats2half2_rn(v.x, v.y);
    }
    for (size_t i = i0; i < 2097152u; i += stride) {
        float2 v = ((const float2*)Whh)[i];
        ((__half2*)g_Whh)[i] = __floats2half2_rn(v.x, v.y);
    }
    for (size_t i = i0; i < 4096u; i += stride) g_bias[i] = bih[i] + bhh[i];
    __half2 z2 = __float2half2_rn(0.f);
    for (size_t i = i0; i < 262144u; i += stride) {
        ((__half2*)g_h)[i] = z2;   // 262144 half2 == both 256x1024 fp16 buffers
        g_c[i] = 0.f;
    }
    if (i0 == 0) g_bar = 0u;
}

// ------------------------- phase A: x @ W_ih^T -----------------------------
// M=131072 (b*512+t), K=512, N=4096. CTA tile 128x128, 8 warps (2m x 4n),
// warp tile 64x32 -> 4 m-atoms x 4 n-atoms of m16n8k16.
__global__ __launch_bounds__(256) void xproj_kernel() {
    __shared__ __align__(16) __half xs[128][72];
    __shared__ __align__(16) __half ws[128][72];
    const int tid = threadIdx.x, lane = tid & 31, warp = tid >> 5;
    const int n0 = blockIdx.x * 128, m0 = blockIdx.y * 128;
    const int wm = warp >> 2, wn = warp & 3;

    float acc[4][4][4];
#pragma unroll
    for (int a = 0; a < 4; ++a)
#pragma unroll
        for (int b = 0; b < 4; ++b)
#pragma unroll
            for (int c = 0; c < 4; ++c) acc[a][b][c] = 0.f;

    for (int kc = 0; kc < 8; ++kc) {
        __syncthreads();
        const __half* xsrc = g_x + (size_t)m0 * 512 + kc * 64;
        const __half* wsrc = g_Wih + (size_t)n0 * 512 + kc * 64;
        for (int i = tid; i < 1024; i += 256) {
            int r = i >> 3, v = i & 7;
            *(uint4*)(&xs[r][v * 8]) = *(const uint4*)(xsrc + (size_t)r * 512 + v * 8);
            *(uint4*)(&ws[r][v * 8]) = *(const uint4*)(wsrc + (size_t)r * 512 + v * 8);
        }
        __syncthreads();
#pragma unroll
        for (int k16 = 0; k16 < 4; ++k16) {
            const int kk = k16 * 16;
            unsigned af[4][4], bf[4][2];
#pragma unroll
            for (int ma = 0; ma < 4; ++ma)
                ldmx4(af[ma][0], af[ma][1], af[ma][2], af[ma][3],
                      &xs[wm * 64 + ma * 16 + (lane & 15)][kk + (lane >> 4) * 8]);
#pragma unroll
            for (int pp = 0; pp < 2; ++pp) {
                unsigned d0, d1, d2, d3;
                ldmx4(d0, d1, d2, d3,
                      &ws[wn * 32 + pp * 16 + ((lane >> 3) & 1) * 8 + (lane & 7)]
                         [kk + (lane >> 4) * 8]);
                bf[pp * 2 + 0][0] = d0; bf[pp * 2 + 1][0] = d1;
                bf[pp * 2 + 0][1] = d2; bf[pp * 2 + 1][1] = d3;
            }
#pragma unroll
            for (int ma = 0; ma < 4; ++ma)
#pragma unroll
                for (int na = 0; na < 4; ++na)
                    mma16816(acc[ma][na], af[ma], bf[na]);
        }
    }

    // store fp32 xW with bias, layout [t][b][unit]; 128-wide tile is in one gate
    const int gate = n0 >> 10;
    float* xw = (gate == 0) ? g_xwi : (gate == 1) ? g_xwf
              : (gate == 2) ? g_xwg : g_xwo;
    const int nu0 = n0 & 1023;
#pragma unroll
    for (int ma = 0; ma < 4; ++ma)
#pragma unroll
        for (int na = 0; na < 4; ++na) {
            int m  = m0 + wm * 64 + ma * 16 + (lane >> 2);
            int nu = nu0 + wn * 32 + na * 8 + ((lane & 3) << 1);
            int bb = m >> 9, tt = m & 511;
            float bs0 = g_bias[(gate << 10) + nu];
            float bs1 = g_bias[(gate << 10) + nu + 1];
            size_t o0 = ((size_t)tt * 256 + bb) * 1024 + nu;
            *(float2*)(xw + o0) =
                make_float2(acc[ma][na][0] + bs0, acc[ma][na][1] + bs1);
            size_t o1 = ((size_t)(tt + 8) * 256 + bb) * 1024 + nu;
            *(float2*)(xw + o1) =
                make_float2(acc[ma][na][2] + bs0, acc[ma][na][3] + bs1);
        }
}

// --------------------- phase B: persistent recurrence ----------------------
// 128 CTAs = 2 M-tiles(128 batch rows) x 64 N-tiles(16 units -> 64 gate cols).
// Smem: Ws [64][1032] fp16 (W_hh slice, all K, stays resident 512 steps),
//       hs [128][72] fp16 / zs [128][68] fp32 (aliased region).
#define REC_SMEM (64 * 1032 * 2 + 128 * 68 * 4)
__global__ __launch_bounds__(256, 1) void lstm_rec_kernel() {
    extern __shared__ __align__(16) unsigned char smem_raw[];
    __half* Ws = (__half*)smem_raw;                        // 132096 B
    __half* hs = (__half*)(smem_raw + 64 * 1032 * 2);      // [128][72] fp16
    float*  zs = (float*)(smem_raw + 64 * 1032 * 2);       // [128][68] fp32

    const int tid = threadIdx.x, lane = tid & 31, warp = tid >> 5;
    const int nt = blockIdx.x & 63, mt = blockIdx.x >> 6;
    const int h0 = nt * 16, m0 = mt * 128;
    const int wm = warp >> 1, wn = warp & 1;   // warp tile 32m x 32n

    // load W_hh slice: smem row r <-> gate (r>>4), unit h0+(r&15); full K=1024
    for (int i = tid; i < 8192; i += 256) {
        int r = i >> 7, v = i & 127;
        int gr = ((r >> 4) << 10) + h0 + (r & 15);
        *(uint4*)(Ws + r * 1032 + v * 8) =
            *(const uint4*)(g_Whh + (size_t)gr * 1024 + v * 8);
    }

    const int jj = tid & 15, rg = tid >> 4;

    for (int t = 0; t < 512; ++t) {
        const __half* hin = g_h + (size_t)(t & 1) * 262144;
        float acc[2][4][4];
#pragma unroll
        for (int a = 0; a < 2; ++a)
#pragma unroll
            for (int b = 0; b < 4; ++b)
#pragma unroll
                for (int c = 0; c < 4; ++c) acc[a][b][c] = 0.f;

        for (int kc = 0; kc < 16; ++kc) {
            __syncthreads();
            const __half* src = hin + (size_t)m0 * 1024 + kc * 64;
            for (int i = tid; i < 1024; i += 256) {
                int r = i >> 3, v = i & 7;
                // __ldcg: bypass L1 — h is written by other SMs (L1 incoherent)
                uint4 val = __ldcg((const uint4*)(src + (size_t)r * 1024 + v * 8));
                *(uint4*)(hs + r * 72 + v * 8) = val;
            }
            __syncthreads();
#pragma unroll
            for (int k16 = 0; k16 < 4; ++k16) {
                const int kk = kc * 64 + k16 * 16;    // offset into full-K Ws
                const int hk = k16 * 16;              // offset into 64-wide hs
                unsigned af[2][4], bf[4][2];
#pragma unroll
                for (int ma = 0; ma < 2; ++ma)
                    ldmx4(af[ma][0], af[ma][1], af[ma][2], af[ma][3],
                          hs + (wm * 32 + ma * 16 + (lane & 15)) * 72
                             + hk + (lane >> 4) * 8);
#pragma unroll
                for (int pp = 0; pp < 2; ++pp) {
                    unsigned d0, d1, d2, d3;
                    ldmx4(d0, d1, d2, d3,
                          Ws + (wn * 32 + pp * 16 + ((lane >> 3) & 1) * 8
                                + (lane & 7)) * 1032 + kk + (lane >> 4) * 8);
                    bf[pp * 2 + 0][0] = d0; bf[pp * 2 + 1][0] = d1;
                    bf[pp * 2 + 0][1] = d2; bf[pp * 2 + 1][1] = d3;
                }
#pragma unroll
                for (int ma = 0; ma < 2; ++ma)
#pragma unroll
                    for (int na = 0; na < 4; ++na)
                        mma16816(acc[ma][na], af[ma], bf[na]);
            }
        }
        __syncthreads();   // all warps done with hs before zs overwrite
#pragma unroll
        for (int ma = 0; ma < 2; ++ma)
#pragma unroll
            for (int na = 0; na < 4; ++na) {
                int m = wm * 32 + ma * 16 + (lane >> 2);
                int n = wn * 32 + na * 8 + ((lane & 3) << 1);
                zs[m * 68 + n]           = acc[ma][na][0];
                zs[m * 68 + n + 1]       = acc[ma][na][1];
                zs[(m + 8) * 68 + n]     = acc[ma][na][2];
                zs[(m + 8) * 68 + n + 1] = acc[ma][na][3];
            }
        __syncthreads();

        // pointwise: gates, cell, hidden (all fp32 except stored h)
#pragma unroll
        for (int s = 0; s < 8; ++s) {
            int r = rg + s * 16;
            int b = m0 + r;
            size_t xo = ((size_t)t * 256 + b) * 1024 + h0 + jj;
            float zi = zs[r * 68 + jj]      + g_xwi[xo];
            float zf = zs[r * 68 + 16 + jj] + g_xwf[xo];
            float zg = zs[r * 68 + 32 + jj] + g_xwg[xo];
            float zo = zs[r * 68 + 48 + jj] + g_xwo[xo];
            float ig = fsig(zi), fg = fsig(zf), gg = ftanh(zg), og = fsig(zo);
            size_t ci = (size_t)b * 1024 + h0 + jj;
            float cn = fg * g_c[ci] + ig * gg;
            g_c[ci] = cn;
            float hn = og * ftanh(cn);
            g_h[(size_t)((t + 1) & 1) * 262144 + ci] = __float2half(hn);
            if (t == 511) g_hT[ci] = hn;
        }

        // grid barrier (monotonic counter; 128 CTAs all co-resident)
        if (t < 511) {
            __syncthreads();
            if (tid == 0) {
                __threadfence();
                atomicAdd(&g_bar, 1u);
                unsigned target = 128u * (unsigned)(t + 1);
                volatile unsigned* bp = &g_bar;
                while (*bp < target) { }
                __threadfence();
            }
            __syncthreads();
        }
    }
}

// ------------------------------ phase C: FC --------------------------------
__global__ __launch_bounds__(256) void fc_kernel(const float* __restrict__ Wfc,
                                                 const float* __restrict__ bfc,
                                                 float* __restrict__ out) {
    __shared__ float As[16][17];
    __shared__ float Bs[16][17];
    const int tx = threadIdx.x, ty = threadIdx.y;
    const int row = blockIdx.y * 16 + ty;   // batch
    const int col = blockIdx.x * 16 + tx;   // out unit
    float acc = 0.f;
    for (int k0 = 0; k0 < 1024; k0 += 16) {
        As[ty][tx] = g_hT[(size_t)row * 1024 + k0 + tx];
        Bs[ty][tx] = Wfc[(size_t)(blockIdx.x * 16 + ty) * 1024 + k0 + tx];
        __syncthreads();
#pragma unroll
        for (int k = 0; k < 16; ++k) acc += As[ty][k] * Bs[tx][k];
        __syncthreads();
    }
    out[(size_t)row * 512 + col] = acc + bfc[col];
}

// ------------------------------- launcher ----------------------------------
extern "C" void kernel_launch(void* const* d_in, const int* in_sizes, int n_in,
                              void* d_out, int out_size) {
    const float* x   = (const float*)d_in[0];
    const float* Wih = (const float*)d_in[1];
    const float* Whh = (const float*)d_in[2];
    const float* bih = (const float*)d_in[3];
    const float* bhh = (const float*)d_in[4];
    const float* Wfc = (const float*)d_in[5];
    const float* bfc = (const float*)d_in[6];

    cudaFuncSetAttribute(lstm_rec_kernel,
                         cudaFuncAttributeMaxDynamicSharedMemorySize, REC_SMEM);

    prep_kernel<<<4096, 256>>>(x, Wih, Whh, bih, bhh);
    xproj_kernel<<<dim3(32, 1024), 256>>>();
    lstm_rec_kernel<<<128, 256, REC_SMEM>>>();
    fc_kernel<<<dim3(32, 16), dim3(16, 16)>>>(Wfc, bfc, (float*)d_out);
}

// round 7
// speedup vs baseline: 2.2165x; 2.2165x over previous
#include <cuda_runtime.h>
#include <cuda_fp16.h>
#include <cstdint>
#include <cstddef>

// ---------------------------------------------------------------------------
// LSTM: x[256,512,512] -> LSTM(H=1024), last hidden -> FC(512). out fp32 [256,512]
// prep -> xproj (mma.sync fp16, cp.async 2-stage) ->
// persistent recurrence (W_hh smem-stationary, cp.async h pipeline, c in regs,
// xW prefetched, grid barrier per step) -> fp32 FC
// ---------------------------------------------------------------------------

#define DEVFN __device__ __forceinline__

// ------------------------- static device scratch ---------------------------
__device__ __half  g_x[67108864];        // x fp16 [b*512+t][512]
__device__ __half  g_Wih[2097152];       // W_ih fp16 [4096][512]
__device__ __half  g_Whh[4194304];       // W_hh fp16 [4096][1024]
__device__ float   g_bias[4096];         // b_ih + b_hh
__device__ float   g_xwi[134217728];     // per-gate xW fp32, [t][b][unit]
__device__ float   g_xwf[134217728];
__device__ float   g_xwg[134217728];
__device__ float   g_xwo[134217728];
__device__ __half  g_h[2 * 262144];      // double-buffered hidden fp16 [b][u]
__device__ float   g_hT[262144];         // final hidden fp32
__device__ unsigned g_bar;               // grid barrier (monotonic)

// ------------------------------ helpers ------------------------------------
DEVFN void ldmx4(unsigned &r0, unsigned &r1, unsigned &r2, unsigned &r3,
                 const void* p) {
    unsigned a = (unsigned)__cvta_generic_to_shared(p);
    asm volatile("ldmatrix.sync.aligned.m8n8.x4.shared.b16 {%0,%1,%2,%3}, [%4];"
                 : "=r"(r0), "=r"(r1), "=r"(r2), "=r"(r3) : "r"(a));
}

DEVFN void mma16816(float* c, const unsigned* a, const unsigned* b) {
    asm volatile(
        "mma.sync.aligned.m16n8k16.row.col.f32.f16.f16.f32 "
        "{%0,%1,%2,%3}, {%4,%5,%6,%7}, {%8,%9}, {%0,%1,%2,%3};"
        : "+f"(c[0]), "+f"(c[1]), "+f"(c[2]), "+f"(c[3])
        : "r"(a[0]), "r"(a[1]), "r"(a[2]), "r"(a[3]), "r"(b[0]), "r"(b[1]));
}

// cp.async 16B, L2-only (.cg) — required for cross-SM h coherence
DEVFN void cpa16(void* smem, const void* gmem) {
    unsigned a = (unsigned)__cvta_generic_to_shared(smem);
    asm volatile("cp.async.cg.shared.global [%0], [%1], 16;" :: "r"(a), "l"(gmem));
}
DEVFN void cpcommit() { asm volatile("cp.async.commit_group;"); }
template <int N> DEVFN void cpwait() {
    asm volatile("cp.async.wait_group %0;" :: "n"(N));
}

DEVFN float fsig(float x)  { return 1.f / (1.f + __expf(-x)); }
DEVFN float ftanh(float x) { return 1.f - 2.f / (__expf(2.f * x) + 1.f); }

// ------------------------------- prep kernel -------------------------------
__global__ void prep_kernel(const float* __restrict__ x,
                            const float* __restrict__ Wih,
                            const float* __restrict__ Whh,
                            const float* __restrict__ bih,
                            const float* __restrict__ bhh) {
    size_t i0 = (size_t)blockIdx.x * blockDim.x + threadIdx.x;
    size_t stride = (size_t)gridDim.x * blockDim.x;
    for (size_t i = i0; i < 33554432u; i += stride) {
        float2 v = ((const float2*)x)[i];
        ((__half2*)g_x)[i] = __floats2half2_rn(v.x, v.y);
    }
    for (size_t i = i0; i < 1048576u; i += stride) {
        float2 v = ((const float2*)Wih)[i];
        ((__half2*)g_Wih)[i] = __floats2half2_rn(v.x, v.y);
    }
    for (size_t i = i0; i < 2097152u; i += stride) {
        float2 v = ((const float2*)Whh)[i];
        ((__half2*)g_Whh)[i] = __floats2half2_rn(v.x, v.y);
    }
    for (size_t i = i0; i < 4096u; i += stride) g_bias[i] = bih[i] + bhh[i];
    __half2 z2 = __float2half2_rn(0.f);
    for (size_t i = i0; i < 262144u; i += stride)
        ((__half2*)g_h)[i] = z2;   // zero both 256x1024 fp16 h buffers
    if (i0 == 0) g_bar = 0u;
}

// ------------------------- phase A: x @ W_ih^T -----------------------------
// M=131072 (b*512+t), K=512, N=4096. CTA tile 128x128, 8 warps (2m x 4n),
// warp tile 64x32. 2-stage cp.async pipeline over 8 K-chunks of 64.
#define XP_SMEM (2 * 128 * 72 * 2 * 2)   // xs[2][128][72] + ws[2][128][72]
__global__ __launch_bounds__(256) void xproj_kernel() {
    extern __shared__ __align__(16) unsigned char xsm[];
    __half* xs = (__half*)xsm;                       // [2][128][72]
    __half* ws = (__half*)(xsm + 2 * 128 * 72 * 2);  // [2][128][72]
    const int tid = threadIdx.x, lane = tid & 31, warp = tid >> 5;
    const int n0 = blockIdx.x * 128, m0 = blockIdx.y * 128;
    const int wm = warp >> 2, wn = warp & 3;
    const int lr = tid >> 1, lv = (tid & 1) * 4;     // 2 rows/thread, 4 v-slots

    float acc[4][4][4];
#pragma unroll
    for (int a = 0; a < 4; ++a)
#pragma unroll
        for (int b = 0; b < 4; ++b)
#pragma unroll
            for (int c = 0; c < 4; ++c) acc[a][b][c] = 0.f;

    const __half* xbase = g_x + (size_t)m0 * 512;
    const __half* wbase = g_Wih + (size_t)n0 * 512;

    auto issue = [&](int kc) {
        __half* xd = xs + (kc & 1) * 9216;
        __half* wd = ws + (kc & 1) * 9216;
        const __half* xsrc = xbase + kc * 64;
        const __half* wsrc = wbase + kc * 64;
#pragma unroll
        for (int q = 0; q < 4; ++q) {   // 1024 uint4 per array / 256 threads
            int r = lr, v = lv + (q & 3);  // q in 0..3 covers 4 of 8 v per row
            // two rows per thread: rows lr and lr+64? use r = (tid>>1)+ (q>=... )
            (void)r; (void)v;
        }
        // simpler: 4 vectors each for xs and ws, linear index
#pragma unroll
        for (int q = 0; q < 4; ++q) {
            int i = tid + q * 256;          // 0..1023
            int r = i >> 3, v = i & 7;
            cpa16(xd + r * 72 + v * 8, xsrc + (size_t)r * 512 + v * 8);
            cpa16(wd + r * 72 + v * 8, wsrc + (size_t)r * 512 + v * 8);
        }
    };

    issue(0); cpcommit();
    for (int kc = 0; kc < 8; ++kc) {
        if (kc < 7) { issue(kc + 1); cpcommit(); cpwait<1>(); }
        else        { cpwait<0>(); }
        __syncthreads();
        const __half* xb = xs + (kc & 1) * 9216;
        const __half* wb = ws + (kc & 1) * 9216;
#pragma unroll
        for (int k16 = 0; k16 < 4; ++k16) {
            const int kk = k16 * 16;
            unsigned af[4][4], bf[4][2];
#pragma unroll
            for (int ma = 0; ma < 4; ++ma)
                ldmx4(af[ma][0], af[ma][1], af[ma][2], af[ma][3],
                      xb + (wm * 64 + ma * 16 + (lane & 15)) * 72
                         + kk + (lane >> 4) * 8);
#pragma unroll
            for (int pp = 0; pp < 2; ++pp) {
                unsigned d0, d1, d2, d3;
                ldmx4(d0, d1, d2, d3,
                      wb + (wn * 32 + pp * 16 + ((lane >> 3) & 1) * 8
                            + (lane & 7)) * 72 + kk + (lane >> 4) * 8);
                bf[pp * 2 + 0][0] = d0; bf[pp * 2 + 1][0] = d1;
                bf[pp * 2 + 0][1] = d2; bf[pp * 2 + 1][1] = d3;
            }
#pragma unroll
            for (int ma = 0; ma < 4; ++ma)
#pragma unroll
                for (int na = 0; na < 4; ++na)
                    mma16816(acc[ma][na], af[ma], bf[na]);
        }
        __syncthreads();
    }

    // store fp32 xW with bias, layout [t][b][unit]; 128-wide tile is in one gate
    const int gate = n0 >> 10;
    float* xw = (gate == 0) ? g_xwi : (gate == 1) ? g_xwf
              : (gate == 2) ? g_xwg : g_xwo;
    const int nu0 = n0 & 1023;
#pragma unroll
    for (int ma = 0; ma < 4; ++ma)
#pragma unroll
        for (int na = 0; na < 4; ++na) {
            int m  = m0 + wm * 64 + ma * 16 + (lane >> 2);
            int nu = nu0 + wn * 32 + na * 8 + ((lane & 3) << 1);
            int bb = m >> 9, tt = m & 511;
            float bs0 = g_bias[(gate << 10) + nu];
            float bs1 = g_bias[(gate << 10) + nu + 1];
            size_t o0 = ((size_t)tt * 256 + bb) * 1024 + nu;
            *(float2*)(xw + o0) =
                make_float2(acc[ma][na][0] + bs0, acc[ma][na][1] + bs1);
            size_t o1 = ((size_t)(tt + 8) * 256 + bb) * 1024 + nu;
            *(float2*)(xw + o1) =
                make_float2(acc[ma][na][2] + bs0, acc[ma][na][3] + bs1);
        }
}

// --------------------- phase B: persistent recurrence ----------------------
// 128 CTAs = 2 M-tiles(128 batch rows) x 64 N-tiles(16 units -> 64 gate cols).
// Smem: Ws [64][1032] fp16 (stationary), hs [2][128][72] fp16 (pipeline),
//       zs [128][68] fp32. Cell state in registers. xW prefetched per step.
#define REC_SMEM (64 * 1032 * 2 + 2 * 128 * 72 * 2 + 128 * 68 * 4)
__global__ __launch_bounds__(256, 1) void lstm_rec_kernel() {
    extern __shared__ __align__(16) unsigned char smem_raw[];
    __half* Ws = (__half*)smem_raw;                              // 132096 B
    __half* hs = (__half*)(smem_raw + 64 * 1032 * 2);            // [2][128][72]
    float*  zs = (float*)(smem_raw + 64 * 1032 * 2 + 2 * 128 * 72 * 2);

    const int tid = threadIdx.x, lane = tid & 31, warp = tid >> 5;
    const int nt = blockIdx.x & 63, mt = blockIdx.x >> 6;
    const int h0 = nt * 16, m0 = mt * 128;
    const int wm = warp >> 1, wn = warp & 1;   // warp tile 32m x 32n

    // load W_hh slice: smem row r <-> gate (r>>4), unit h0+(r&15); full K=1024
    for (int i = tid; i < 8192; i += 256) {
        int r = i >> 7, v = i & 127;
        int gr = ((r >> 4) << 10) + h0 + (r & 15);
        *(uint4*)(Ws + r * 1032 + v * 8) =
            *(const uint4*)(g_Whh + (size_t)gr * 1024 + v * 8);
    }

    const int jj = tid & 15, rg = tid >> 4;
    float creg[8];
#pragma unroll
    for (int s = 0; s < 8; ++s) creg[s] = 0.f;

    for (int t = 0; t < 512; ++t) {
        const __half* hin = g_h + (size_t)(t & 1) * 262144;

        // prefetch xW for this step (independent of h — hides DRAM latency)
        float xwi[8], xwf[8], xwg[8], xwo[8];
#pragma unroll
        for (int s = 0; s < 8; ++s) {
            size_t xo = ((size_t)t * 256 + (m0 + rg + s * 16)) * 1024 + h0 + jj;
            xwi[s] = g_xwi[xo]; xwf[s] = g_xwf[xo];
            xwg[s] = g_xwg[xo]; xwo[s] = g_xwo[xo];
        }

        float acc[2][4][4];
#pragma unroll
        for (int a = 0; a < 2; ++a)
#pragma unroll
            for (int b = 0; b < 4; ++b)
#pragma unroll
                for (int c = 0; c < 4; ++c) acc[a][b][c] = 0.f;

        auto issue = [&](int kc) {
            __half* dst = hs + (kc & 1) * 9216;
            const __half* src = hin + (size_t)m0 * 1024 + kc * 64;
#pragma unroll
            for (int q = 0; q < 4; ++q) {
                int i = tid + q * 256;      // 0..1023
                int r = i >> 3, v = i & 7;
                cpa16(dst + r * 72 + v * 8, src + (size_t)r * 1024 + v * 8);
            }
        };

        issue(0); cpcommit();
        for (int kc = 0; kc < 16; ++kc) {
            if (kc < 15) { issue(kc + 1); cpcommit(); cpwait<1>(); }
            else         { cpwait<0>(); }
            __syncthreads();
            const __half* hb = hs + (kc & 1) * 9216;
#pragma unroll
            for (int k16 = 0; k16 < 4; ++k16) {
                const int kk = kc * 64 + k16 * 16;    // offset into full-K Ws
                const int hk = k16 * 16;              // offset into 64-wide hs
                unsigned af[2][4], bf[4][2];
#pragma unroll
                for (int ma = 0; ma < 2; ++ma)
                    ldmx4(af[ma][0], af[ma][1], af[ma][2], af[ma][3],
                          hb + (wm * 32 + ma * 16 + (lane & 15)) * 72
                             + hk + (lane >> 4) * 8);
#pragma unroll
                for (int pp = 0; pp < 2; ++pp) {
                    unsigned d0, d1, d2, d3;
                    ldmx4(d0, d1, d2, d3,
                          Ws + (wn * 32 + pp * 16 + ((lane >> 3) & 1) * 8
                                + (lane & 7)) * 1032 + kk + (lane >> 4) * 8);
                    bf[pp * 2 + 0][0] = d0; bf[pp * 2 + 1][0] = d1;
                    bf[pp * 2 + 0][1] = d2; bf[pp * 2 + 1][1] = d3;
                }
#pragma unroll
                for (int ma = 0; ma < 2; ++ma)
#pragma unroll
                    for (int na = 0; na < 4; ++na)
                        mma16816(acc[ma][na], af[ma], bf[na]);
            }
            __syncthreads();
        }

        // spill z to smem (per-warp exclusive tiles)
#pragma unroll
        for (int ma = 0; ma < 2; ++ma)
#pragma unroll
            for (int na = 0; na < 4; ++na) {
                int m = wm * 32 + ma * 16 + (lane >> 2);
                int n = wn * 32 + na * 8 + ((lane & 3) << 1);
                zs[m * 68 + n]           = acc[ma][na][0];
                zs[m * 68 + n + 1]       = acc[ma][na][1];
                zs[(m + 8) * 68 + n]     = acc[ma][na][2];
                zs[(m + 8) * 68 + n + 1] = acc[ma][na][3];
            }
        __syncthreads();

        // pointwise: gates, cell (regs), hidden
#pragma unroll
        for (int s = 0; s < 8; ++s) {
            int r = rg + s * 16;
            int b = m0 + r;
            float zi = zs[r * 68 + jj]      + xwi[s];
            float zf = zs[r * 68 + 16 + jj] + xwf[s];
            float zg = zs[r * 68 + 32 + jj] + xwg[s];
            float zo = zs[r * 68 + 48 + jj] + xwo[s];
            float ig = fsig(zi), fg = fsig(zf), gg = ftanh(zg), og = fsig(zo);
            float cn = fg * creg[s] + ig * gg;
            creg[s] = cn;
            float hn = og * ftanh(cn);
            size_t ci = (size_t)b * 1024 + h0 + jj;
            g_h[(size_t)((t + 1) & 1) * 262144 + ci] = __float2half(hn);
            if (t == 511) g_hT[ci] = hn;
        }

        // grid barrier (monotonic counter; 128 CTAs all co-resident)
        if (t < 511) {
            __syncthreads();
            if (tid == 0) {
                __threadfence();
                atomicAdd(&g_bar, 1u);
                unsigned target = 128u * (unsigned)(t + 1);
                volatile unsigned* bp = &g_bar;
                while (*bp < target) { }
                __threadfence();
            }
            __syncthreads();
        }
    }
}

// ------------------------------ phase C: FC --------------------------------
__global__ __launch_bounds__(256) void fc_kernel(const float* __restrict__ Wfc,
                                                 const float* __restrict__ bfc,
                                                 float* __restrict__ out) {
    __shared__ float As[16][17];
    __shared__ float Bs[16][17];
    const int tx = threadIdx.x, ty = threadIdx.y;
    const int row = blockIdx.y * 16 + ty;   // batch
    const int col = blockIdx.x * 16 + tx;   // out unit
    float acc = 0.f;
    for (int k0 = 0; k0 < 1024; k0 += 16) {
        As[ty][tx] = g_hT[(size_t)row * 1024 + k0 + tx];
        Bs[ty][tx] = Wfc[(size_t)(blockIdx.x * 16 + ty) * 1024 + k0 + tx];
        __syncthreads();
#pragma unroll
        for (int k = 0; k < 16; ++k) acc += As[ty][k] * Bs[tx][k];
        __syncthreads();
    }
    out[(size_t)row * 512 + col] = acc + bfc[col];
}

// ------------------------------- launcher ----------------------------------
extern "C" void kernel_launch(void* const* d_in, const int* in_sizes, int n_in,
                              void* d_out, int out_size) {
    const float* x   = (const float*)d_in[0];
    const float* Wih = (const float*)d_in[1];
    const float* Whh = (const float*)d_in[2];
    const float* bih = (const float*)d_in[3];
    const float* bhh = (const float*)d_in[4];
    const float* Wfc = (const float*)d_in[5];
    const float* bfc = (const float*)d_in[6];

    cudaFuncSetAttribute(xproj_kernel,
                         cudaFuncAttributeMaxDynamicSharedMemorySize, XP_SMEM);
    cudaFuncSetAttribute(lstm_rec_kernel,
                         cudaFuncAttributeMaxDynamicSharedMemorySize, REC_SMEM);

    prep_kernel<<<4096, 256>>>(x, Wih, Whh, bih, bhh);
    xproj_kernel<<<dim3(32, 1024), 256, XP_SMEM>>>();
    lstm_rec_kernel<<<128, 256, REC_SMEM>>>();
    fc_kernel<<<dim3(32, 16), dim3(16, 16)>>>(Wfc, bfc, (float*)d_out);
}